// round 1
// baseline (speedup 1.0000x reference)
#include <cuda_runtime.h>
#include <cstddef>

#define NB 64
#define NT 1024
#define NV 256
#define NS 256
#define ND 24
#define NL 513          // 2*NS+1
#define GAMMA 0.1f
#define NEGF (-1e10f)
#define BIGF (1e10f)

// Scratch (no allocation allowed)
__device__ float g_pred[NB * NT * ND];     // predicted features (B,T,D)
__device__ float g_loss[2 * NB];           // [0..63] ctc per batch, [64..127] sdtw per batch

// ----------------------------------------------------------------------------
// Kernel 1: pred = exp(log_probs) @ fm   (65536 x 256) @ (256 x 24)
// Block: 384 threads = 16 rows x 24 cols per tile iteration.
// fm staged transposed in smem for float4 k-loop; exp staged per 16-row tile.
// ----------------------------------------------------------------------------
__global__ __launch_bounds__(384) void prep_kernel(const float* __restrict__ lp,
                                                   const float* __restrict__ fm) {
    __shared__ float fmT[ND][264];     // transposed, padded row (264 % 4 == 0)
    __shared__ float eS[16][256];

    int tid = threadIdx.x;
    for (int idx = tid; idx < NV * ND; idx += blockDim.x) {
        int v = idx / ND, d = idx - v * ND;
        fmT[d][v] = fm[idx];
    }
    __syncthreads();

    const int rowsPerBlock = (NB * NT) / gridDim.x;   // 512 with 128 blocks
    const int row0 = blockIdx.x * rowsPerBlock;

    const int r = tid / ND;        // 0..15
    const int d = tid - r * ND;    // 0..23

    for (int rb = 0; rb < rowsPerBlock; rb += 16) {
        // phase 1: exp of 16 rows, coalesced
        for (int idx = tid; idx < 16 * NV; idx += blockDim.x) {
            int rr = idx >> 8, v = idx & 255;
            eS[rr][v] = __expf(lp[(size_t)(row0 + rb + rr) * NV + v]);
        }
        __syncthreads();
        // phase 2: one output per thread, float4 k-loop
        const float4* e4 = reinterpret_cast<const float4*>(eS[r]);
        const float4* f4 = reinterpret_cast<const float4*>(fmT[d]);
        float acc = 0.f;
#pragma unroll
        for (int v4 = 0; v4 < NV / 4; v4++) {
            float4 e = e4[v4];
            float4 f = f4[v4];
            acc += e.x * f.x + e.y * f.y + e.z * f.z + e.w * f.w;
        }
        g_pred[(size_t)(row0 + rb + r) * ND + d] = acc;
        __syncthreads();
    }
}

// ----------------------------------------------------------------------------
// Kernel 2 (fused): blocks 0..63  -> soft-DTW  (per-batch anti-diagonal DP)
//                   blocks 64..127-> CTC forward (per-batch, 513 states)
// Dynamic smem (union):
//   SDTW: pred[1024][25] + pnorm[1024] + 3 x R[257]   = 109,580 B
//   CTC : alpha[2][513] + row[256]                     (fits inside union)
// ----------------------------------------------------------------------------
extern __shared__ float smemf[];

__global__ __launch_bounds__(544) void main_kernel(const float* __restrict__ lp,
                                                   const float* __restrict__ fm,
                                                   const int* __restrict__ targets,
                                                   const int* __restrict__ in_len,
                                                   const int* __restrict__ tg_len) {
    const int tid = threadIdx.x;      // 0..543
    const int bid = blockIdx.x;

    if (bid < NB) {
        // ======================= soft-DTW =======================
        const int b = bid;
        float* predS = smemf;                 // 1024*25
        float* pnorm = predS + NT * 25;       // 1024
        float* RA = pnorm + NT;               // 257
        float* RB = RA + 257;                 // 257
        float* RC = RB + 257;                 // 257

        // stage pred rows (padded to 25 floats -> conflict-free scalar LDS)
        const float* gp = g_pred + (size_t)b * NT * ND;
        for (int idx = tid; idx < NT * ND; idx += blockDim.x) {
            int rr = idx / ND, k = idx - rr * ND;
            predS[rr * 25 + k] = gp[idx];
        }
        __syncthreads();
        // row norms
        for (int rr = tid; rr < NT; rr += blockDim.x) {
            float s = 0.f;
            const float* p = predS + rr * 25;
#pragma unroll
            for (int k = 0; k < ND; k++) { float x = p[k]; s += x * x; }
            pnorm[rr] = s;
        }

        // target features for this thread's column (registers)
        float q2[ND];
        float qc = 0.f;
        if (tid < NS) {
            int label = targets[b * NS + tid];
            const float* fq = fm + (size_t)label * ND;
            float qn = 0.f;
#pragma unroll
            for (int k = 0; k < ND; k++) {
                float q = fq[k];
                q2[k] = -2.f * q;
                qn += q * q;
            }
            qc = qn;
        }

        // init R diagonals: RA = diag 0 (R[0][0]=0), RB = diag 1 (all BIG)
        for (int j = tid; j < 257; j += blockDim.x) {
            RA[j] = (j == 0) ? 0.f : BIGF;
            RB[j] = BIGF;
            RC[j] = BIGF;
        }
        __syncthreads();

        float* Rpp = RA;
        float* Rp  = RB;
        float* Rc  = RC;
        const int jj = tid + 1;   // column index 1..256

        for (int dg = 2; dg <= NT + NS; dg++) {
            if (tid < NS) {
                int i = dg - jj;                   // row index 1..1024
                if (i >= 1 && i <= NT) {
                    const float* p = predS + (i - 1) * 25;
                    float dcost = pnorm[i - 1] + qc;
#pragma unroll
                    for (int k = 0; k < ND; k++) dcost += p[k] * q2[k];
                    float r1 = Rp[jj];        // R[i-1][j]
                    float r2 = Rp[jj - 1];    // R[i][j-1]
                    float r3 = Rpp[jj - 1];   // R[i-1][j-1]
                    float mn = fminf(r1, fminf(r2, r3));
                    float sm = mn - GAMMA * __logf(__expf((mn - r1) * 10.0f) +
                                                   __expf((mn - r2) * 10.0f) +
                                                   __expf((mn - r3) * 10.0f));
                    Rc[jj] = dcost + sm;
                }
            }
            if (tid == NS) Rc[0] = BIGF;     // boundary column j=0
            __syncthreads();
            float* t0 = Rpp; Rpp = Rp; Rp = Rc; Rc = t0;
        }
        if (tid == 0) g_loss[NB + b] = Rp[NS];   // R[T][S]
    } else {
        // ======================= CTC forward =======================
        const int b = bid - NB;
        float* alphaA = smemf;            // 513
        float* alphaB = alphaA + NL;      // 513
        float* row    = alphaB + NL;      // 256

        int exts = 0;
        bool skip = false;
        if (tid < NL) {
            if (tid & 1) {
                int k = (tid - 1) >> 1;
                exts = targets[b * NS + k];
                if (tid >= 3) skip = (exts != targets[b * NS + k - 1]);
            }
        }

        const float* lpb = lp + (size_t)b * NT * NV;

        // t = 0
        for (int v = tid; v < NV; v += blockDim.x) row[v] = lpb[v];
        __syncthreads();
        if (tid < NL) alphaA[tid] = (tid < 2) ? row[exts] : NEGF;
        __syncthreads();

        const int len = in_len[b];
        for (int t = 1; t < len; t++) {
            for (int v = tid; v < NV; v += blockDim.x) row[v] = lpb[(size_t)t * NV + v];
            __syncthreads();
            if (tid < NL) {
                float g  = row[exts];
                float a1 = alphaA[tid];
                float a2 = (tid >= 1) ? alphaA[tid - 1] : NEGF;
                float a3 = skip ? alphaA[tid - 2] : NEGF;
                float m  = fmaxf(a1, fmaxf(a2, a3));
                float v3 = __expf(a1 - m) + __expf(a2 - m) + __expf(a3 - m);
                alphaB[tid] = m + __logf(v3) + g;
            }
            __syncthreads();
            float* tmp = alphaA; alphaA = alphaB; alphaB = tmp;
        }

        if (tid == 0) {
            int tl = tg_len[b];
            float aL = alphaA[2 * tl];       // alpha[l-1], l = 2*tl+1
            float aP = alphaA[2 * tl - 1];   // alpha[l-2]
            float m  = fmaxf(aL, aP);
            float ll = m + __logf(__expf(aL - m) + __expf(aP - m));
            g_loss[b] = -ll / (float)tl;
        }
    }
}

// ----------------------------------------------------------------------------
// Kernel 3: final reduction to scalar
// ----------------------------------------------------------------------------
__global__ void reduce_kernel(float* __restrict__ out) {
    if (threadIdx.x == 0) {
        float s_ctc = 0.f, s_dtw = 0.f;
#pragma unroll
        for (int b = 0; b < NB; b++) s_ctc += g_loss[b];
#pragma unroll
        for (int b = 0; b < NB; b++) s_dtw += g_loss[NB + b];
        out[0] = s_ctc / (float)NB + s_dtw / (float)NB;
    }
}

extern "C" void kernel_launch(void* const* d_in, const int* in_sizes, int n_in,
                              void* d_out, int out_size) {
    const float* lp  = (const float*)d_in[0];  // (B,T,V) f32
    const float* fm  = (const float*)d_in[1];  // (V,D)   f32
    const int*   tgt = (const int*)  d_in[2];  // (B,S)   i32
    const int*   il  = (const int*)  d_in[3];  // (B,)    i32
    const int*   tl  = (const int*)  d_in[4];  // (B,)    i32
    float* out = (float*)d_out;

    const size_t smem = (size_t)(NT * 25 + NT + 3 * 257) * sizeof(float); // 109,580 B
    cudaFuncSetAttribute(main_kernel, cudaFuncAttributeMaxDynamicSharedMemorySize, (int)smem);

    prep_kernel<<<128, 384>>>(lp, fm);
    main_kernel<<<2 * NB, 544, smem>>>(lp, fm, tgt, il, tl);
    reduce_kernel<<<1, 32>>>(out);
}

// round 3
// speedup vs baseline: 1.0703x; 1.0703x over previous
#include <cuda_runtime.h>
#include <cstddef>

#define NB 64
#define NT 1024
#define NV 256
#define NS 256
#define ND 24
#define NL 513          // 2*NS+1
#define DGP 1284        // padded diagonal dimension (multiple of 4, >= NT+NS+1)
#define GAMMA 0.1f
#define NEGF (-1e10f)
#define BIGF (1e10f)

// Scratch (no allocation allowed)
__device__ float g_pred[NB * NT * ND];          // predicted features (B,T,D)
__device__ float g_cost[(size_t)NB * NS * DGP]; // sdtw cost, diag layout [b][j][dg], dg=i+j+2 (0-based i,j)
__device__ float g_loss[2 * NB];                // [0..63] ctc, [64..127] sdtw

// median-free safe 3-way helpers: mn <= md <= mx computed with pure min/max
__device__ __forceinline__ void sort3(float a, float b, float c,
                                      float& mn, float& md, float& mx) {
    float t1 = fminf(a, b);
    float t2 = fmaxf(a, b);
    mn = fminf(t1, c);
    mx = fmaxf(t2, c);
    md = fmaxf(t1, fminf(t2, c));
}

// ----------------------------------------------------------------------------
// Kernel 1: pred = exp(log_probs) @ fm   (65536 x 256) @ (256 x 24)
// Register-tiled: 256 threads, block tile = 128 rows x 24 dims, K chunked by 64.
// ----------------------------------------------------------------------------
__global__ __launch_bounds__(256) void prep_kernel(const float* __restrict__ lp,
                                                   const float* __restrict__ fm) {
    __shared__ float eS[64 * 129];
    __shared__ float fmS[64 * 25];

    const int tid = threadIdx.x;
    const int row0 = blockIdx.x * 128;
    const int rg = tid >> 3;       // 0..31 (row group of 4)
    const int dgrp = tid & 7;      // 0..7  (dim group of 3)

    float acc[4][3];
#pragma unroll
    for (int i = 0; i < 4; i++)
#pragma unroll
        for (int j = 0; j < 3; j++) acc[i][j] = 0.f;

    for (int v0 = 0; v0 < NV; v0 += 64) {
        for (int idx = tid; idx < 64 * 24; idx += 256) {
            int v = idx / 24, d = idx - v * 24;
            fmS[v * 25 + d] = fm[(v0 + v) * ND + d];
        }
        for (int idx = tid; idx < 128 * 64; idx += 256) {
            int r = idx >> 6, v = idx & 63;
            eS[v * 129 + r] = __expf(lp[(size_t)(row0 + r) * NV + v0 + v]);
        }
        __syncthreads();

#pragma unroll 4
        for (int v = 0; v < 64; v++) {
            float e0 = eS[v * 129 + rg * 4 + 0];
            float e1 = eS[v * 129 + rg * 4 + 1];
            float e2 = eS[v * 129 + rg * 4 + 2];
            float e3 = eS[v * 129 + rg * 4 + 3];
            float f0 = fmS[v * 25 + dgrp * 3 + 0];
            float f1 = fmS[v * 25 + dgrp * 3 + 1];
            float f2 = fmS[v * 25 + dgrp * 3 + 2];
            acc[0][0] += e0 * f0; acc[0][1] += e0 * f1; acc[0][2] += e0 * f2;
            acc[1][0] += e1 * f0; acc[1][1] += e1 * f1; acc[1][2] += e1 * f2;
            acc[2][0] += e2 * f0; acc[2][1] += e2 * f1; acc[2][2] += e2 * f2;
            acc[3][0] += e3 * f0; acc[3][1] += e3 * f1; acc[3][2] += e3 * f2;
        }
        __syncthreads();
    }

#pragma unroll
    for (int i = 0; i < 4; i++)
#pragma unroll
        for (int j = 0; j < 3; j++)
            g_pred[(size_t)(row0 + rg * 4 + i) * ND + dgrp * 3 + j] = acc[i][j];
}

// ----------------------------------------------------------------------------
// Kernel 2: sdtw cost matrix in diagonal layout.
// cost[b][j][i+j+2] = |p_i|^2 + |q_j|^2 - 2 p_i . q_j   (0-based i in T, j in S)
// ----------------------------------------------------------------------------
__global__ __launch_bounds__(256) void cost_kernel(const float* __restrict__ fm,
                                                   const int* __restrict__ targets) {
    __shared__ float pS[64 * 25];
    __shared__ float qS[128 * 25];
    __shared__ float pn[64];
    __shared__ float qn[128];
    __shared__ int qlab[128];

    const int tid = threadIdx.x;
    const int b = blockIdx.z;
    const int i0 = blockIdx.x * 64;
    const int j0 = blockIdx.y * 128;

    if (tid < 128) qlab[tid] = targets[b * NS + j0 + tid];
    for (int idx = tid; idx < 64 * 24; idx += 256) {
        int r = idx / 24, d = idx - r * 24;
        pS[r * 25 + d] = g_pred[((size_t)b * NT + i0 + r) * ND + d];
    }
    __syncthreads();
    for (int idx = tid; idx < 128 * 24; idx += 256) {
        int c = idx / 24, d = idx - c * 24;
        qS[c * 25 + d] = fm[qlab[c] * ND + d];
    }
    __syncthreads();
    if (tid < 64) {
        float s = 0.f;
#pragma unroll
        for (int d = 0; d < ND; d++) { float x = pS[tid * 25 + d]; s += x * x; }
        pn[tid] = s;
    } else if (tid < 192) {
        int c = tid - 64;
        float s = 0.f;
#pragma unroll
        for (int d = 0; d < ND; d++) { float x = qS[c * 25 + d]; s += x * x; }
        qn[c] = s;
    }
    __syncthreads();

    const int w = tid >> 5;        // i-group: rows w*8..w*8+7
    const int lane = tid & 31;     // j-cols: lane + 32*jj

    float acc[8][4];
#pragma unroll
    for (int i = 0; i < 8; i++)
#pragma unroll
        for (int j = 0; j < 4; j++) acc[i][j] = 0.f;

#pragma unroll
    for (int k = 0; k < ND; k++) {
        float pk[8], qk[4];
#pragma unroll
        for (int i = 0; i < 8; i++) pk[i] = pS[(w * 8 + i) * 25 + k];
#pragma unroll
        for (int j = 0; j < 4; j++) qk[j] = qS[(lane + 32 * j) * 25 + k];
#pragma unroll
        for (int i = 0; i < 8; i++)
#pragma unroll
            for (int j = 0; j < 4; j++) acc[i][j] += pk[i] * qk[j];
    }

#pragma unroll
    for (int j = 0; j < 4; j++) {
        int jl = lane + 32 * j;
        int jg = j0 + jl;
        float qnj = qn[jl];
        size_t base = ((size_t)b * NS + jg) * DGP;
#pragma unroll
        for (int i = 0; i < 8; i++) {
            int ig = i0 + w * 8 + i;
            g_cost[base + (size_t)(ig + jg + 2)] = pn[w * 8 + i] + qnj - 2.f * acc[i][j];
        }
    }
}

// ----------------------------------------------------------------------------
// Kernel 3 (fused DP): blocks 0..63 -> soft-DTW, 64..127 -> CTC forward.
// Register-resident DP state, warp shuffles for neighbors, smem only for
// warp-boundary values (double-buffered by step parity). One barrier per step.
// ----------------------------------------------------------------------------
__global__ __launch_bounds__(544) void main_kernel(const float* __restrict__ lp,
                                                   const int* __restrict__ targets,
                                                   const int* __restrict__ in_len,
                                                   const int* __restrict__ tg_len) {
    const int tid = threadIdx.x;
    const int lane = tid & 31;
    const int w = tid >> 5;
    const int bid = blockIdx.x;

    __shared__ float bndP[2][8];
    __shared__ float bndPP[2][8];
    __shared__ float actc[NL];
    __shared__ float bndA[2][17][2];

    if (bid < NB) {
        // ======================= soft-DTW =======================
        const int b = bid;
        const bool act = (tid < 256);            // warps 0..7 active
        const int jj = tid + 1;                  // column 1..256
        const float* cbase = g_cost + ((size_t)b * NS + (act ? tid : 0)) * DGP;

        float Rp = BIGF, Rpp = BIGF;             // R at (diag-1, j) and (diag-2, j)
        if (tid < 8) { bndP[0][tid] = BIGF; bndP[1][tid] = BIGF;
                       bndPP[0][tid] = BIGF; bndPP[1][tid] = BIGF; }
        __syncthreads();

        float4 cc = *(const float4*)cbase;       // group 0: dg 0..3
        for (int g = 0; g <= 320; g++) {
            float4 cn = cc;
            if (act && g < 320) cn = *(const float4*)(cbase + (size_t)(g + 1) * 4);
#pragma unroll
            for (int k = 0; k < 4; k++) {
                const int dg = g * 4 + k;
                if (act) {
                    float c = (k == 0) ? cc.x : (k == 1) ? cc.y : (k == 2) ? cc.z : cc.w;
                    const int par = dg & 1;
                    float r2 = __shfl_up_sync(0xffffffffu, Rp, 1);
                    float r3 = __shfl_up_sync(0xffffffffu, Rpp, 1);
                    if (lane == 0) {
                        r2 = (w == 0) ? BIGF : bndP[par][w - 1];
                        r3 = (w == 0) ? ((dg == 2) ? 0.f : BIGF) : bndPP[par][w - 1];
                    }
                    float r1 = Rp;
                    float mn, md, mx;
                    sort3(r1, r2, r3, mn, md, mx);   // exact: no cancellation
                    float s = 1.f + __expf((mn - md) * (1.f / GAMMA))
                                  + __expf((mn - mx) * (1.f / GAMMA));
                    const int i = dg - jj;
                    float Rc = (i >= 1 && i <= NT) ? (c + mn - GAMMA * __logf(s)) : BIGF;
                    if (lane == 31) { bndPP[par ^ 1][w] = Rp; bndP[par ^ 1][w] = Rc; }
                    if (dg == NT + NS && tid == NS - 1) g_loss[NB + b] = Rc;
                    Rpp = Rp; Rp = Rc;
                }
                __syncthreads();
            }
            cc = cn;
        }
    } else {
        // ======================= CTC forward =======================
        const int b = bid - NB;
        const int s = (tid < NL) ? tid : (NL - 1);   // clamp for inert threads
        int ext = 0;
        bool skip = false;
        if (s & 1) {
            int kk = (s - 1) >> 1;
            ext = targets[b * NS + kk];
            if (s >= 3) skip = (ext != targets[b * NS + kk - 1]);
        }
        const float* lpb = lp + (size_t)b * NT * NV;

        // t = 0
        float A = (tid < 2) ? __ldg(lpb + ext) : NEGF;
        if (lane >= 30) { bndA[1][w][lane - 30] = A; }
        __syncthreads();

        const int len = in_len[b];

        float gq[4];
#pragma unroll
        for (int k = 0; k < 4; k++) {
            int tt = 1 + k;
            gq[k] = (tt < NT) ? __ldg(lpb + (size_t)tt * NV + ext) : 0.f;
        }

        for (int t0 = 1; t0 < len; t0 += 4) {
            float gn[4];
#pragma unroll
            for (int k = 0; k < 4; k++) {
                int tt = t0 + 4 + k;
                gn[k] = (tt < NT) ? __ldg(lpb + (size_t)tt * NV + ext) : 0.f;
            }
#pragma unroll
            for (int k = 0; k < 4; k++) {
                const int t = t0 + k;
                if (t < len) {                       // uniform across block
                    const int par = t & 1;
                    float a2 = __shfl_up_sync(0xffffffffu, A, 1);
                    float a3 = __shfl_up_sync(0xffffffffu, A, 2);
                    if (lane == 0) {
                        a2 = (w == 0) ? NEGF : bndA[par][w - 1][1];
                        a3 = (w == 0) ? NEGF : bndA[par][w - 1][0];
                    }
                    if (lane == 1) a3 = (w == 0) ? NEGF : bndA[par][w - 1][1];
                    a3 = skip ? a3 : NEGF;
                    float a1 = A;
                    float mn, md, m;
                    sort3(a1, a2, a3, mn, md, m);    // exact: no cancellation
                    float sum = 1.f + __expf(mn - m) + __expf(md - m);
                    A = m + __logf(sum) + gq[k];
                    if (lane >= 30) bndA[par ^ 1][w][lane - 30] = A;
                }
                __syncthreads();
            }
            gq[0] = gn[0]; gq[1] = gn[1]; gq[2] = gn[2]; gq[3] = gn[3];
        }

        if (tid < NL) actc[tid] = A;
        __syncthreads();
        if (tid == 0) {
            int tl = tg_len[b];
            float aL = actc[2 * tl];
            float aP = actc[2 * tl - 1];
            float m = fmaxf(aL, aP);
            float ll = m + __logf(__expf(aL - m) + __expf(aP - m));
            g_loss[b] = -ll / (float)tl;
        }
    }
}

// ----------------------------------------------------------------------------
// Kernel 4: final reduction to scalar
// ----------------------------------------------------------------------------
__global__ void reduce_kernel(float* __restrict__ out) {
    if (threadIdx.x == 0) {
        float s_ctc = 0.f, s_dtw = 0.f;
#pragma unroll
        for (int b = 0; b < NB; b++) s_ctc += g_loss[b];
#pragma unroll
        for (int b = 0; b < NB; b++) s_dtw += g_loss[NB + b];
        out[0] = s_ctc / (float)NB + s_dtw / (float)NB;
    }
}

extern "C" void kernel_launch(void* const* d_in, const int* in_sizes, int n_in,
                              void* d_out, int out_size) {
    const float* lp  = (const float*)d_in[0];  // (B,T,V) f32
    const float* fm  = (const float*)d_in[1];  // (V,D)   f32
    const int*   tgt = (const int*)  d_in[2];  // (B,S)   i32
    const int*   il  = (const int*)  d_in[3];  // (B,)    i32
    const int*   tl  = (const int*)  d_in[4];  // (B,)    i32
    float* out = (float*)d_out;

    prep_kernel<<<512, 256>>>(lp, fm);
    cost_kernel<<<dim3(16, 2, 64), 256>>>(fm, tgt);
    main_kernel<<<2 * NB, 544>>>(lp, tgt, il, tl);
    reduce_kernel<<<1, 32>>>(out);
}